// round 7
// baseline (speedup 1.0000x reference)
#include <cuda_runtime.h>
#include <cstdint>

// MonarchOutProjection:
//   h2[t][b][n]    = sum_m L[b][n][m] * x[t][m*32+b]
//   out[t][i*32+j] = sum_m R[j][i][m] * h2[t][m][j]
//
// R6: stage2 reads h2 slabs directly from global (lane-uniform LDG.128 from
// the [tile][n][b][t] layout -> 2KB contiguous per warp) -- no smem tile, no
// cp.async, one less barrier. os staging uses a dense XOR-swizzled layout.

#define TILE_T 16
#define HROW   516                 // stage1 xs row: 32*16 + 4 pad
#define BUF1_FLOATS 8256           // 16 * 516
#define OS_FLOATS   8192           // 16 t * 32 i * 16 jl (dense, XOR swizzle)

#define SMEM1_BYTES (2 * BUF1_FLOATS * 4)   // 66048
#define SMEM2_BYTES (OS_FLOATS * 4)         // 32768

// g_h2[tile][n][b][t] : idx = tile*16384 + n*512 + b*16 + t
__device__ float g_h2[33554432];

__device__ __forceinline__ unsigned smem_addr(const void* p) {
    return (unsigned)__cvta_generic_to_shared(p);
}
__device__ __forceinline__ void cp_async4(unsigned dst, const float* src) {
    asm volatile("cp.async.ca.shared.global [%0], [%1], 4;" :: "r"(dst), "l"(src));
}
__device__ __forceinline__ void cp_commit() {
    asm volatile("cp.async.commit_group;");
}
__device__ __forceinline__ void cp_wait1() {
    asm volatile("cp.async.wait_group 1;");
}
// acc = a * b + acc  (two independent fp32 FMAs, packed)
__device__ __forceinline__ void ffma2(uint64_t& acc, uint64_t a, uint64_t b) {
    asm("fma.rn.f32x2 %0, %1, %2, %0;" : "+l"(acc) : "l"(a), "l"(b));
}
__device__ __forceinline__ uint64_t splat2(float w) {
    uint64_t r;
    asm("mov.b64 %0, {%1, %1};" : "=l"(r) : "f"(w));
    return r;
}

__global__ __launch_bounds__(512, 2)
void monarch_stage1(const float* __restrict__ x, const float* __restrict__ L,
                    int ntiles) {
    extern __shared__ float sm[];        // buf0|buf1 : xs[bl][m][t], row HROW
    const int tid  = threadIdx.x;
    const int warp = tid >> 5;           // bl
    const int lane = tid & 31;           // n
    const int half   = blockIdx.x & 1;
    const int bstart = half * 16;
    const int b      = bstart + warp;

    // Weights: Lreg[m] = L[b][n=lane][m]
    float Lreg[32];
    const float4* Lp = (const float4*)(L + b * 1024 + lane * 32);
    #pragma unroll
    for (int q = 0; q < 8; q++) {
        float4 v = Lp[q];
        Lreg[4*q+0] = v.x; Lreg[4*q+1] = v.y; Lreg[4*q+2] = v.z; Lreg[4*q+3] = v.w;
    }

    const unsigned sbase = smem_addr(sm);
    const int tstride = gridDim.x >> 1;
    const int tile0   = blockIdx.x >> 1;

    // Copy mapping (fixed): thread handles (cbl, cm), 16 t-values, 4B each.
    const int cbl = tid & 15, cm = (tid >> 4) & 31;

    if (tile0 < ntiles) {
        const float* srcb = x + (tile0 * TILE_T) * 1024 + cm * 32 + bstart + cbl;
        unsigned dstb = sbase + (cbl * HROW + cm * 16) * 4;
        #pragma unroll
        for (int k = 0; k < 16; k++)
            cp_async4(dstb + k * 4, srcb + k * 1024);
    }
    cp_commit();

    int cur = 0;
    for (int tile = tile0; tile < ntiles; tile += tstride) {
        int nxt = tile + tstride;
        if (nxt < ntiles) {
            const float* srcb = x + (nxt * TILE_T) * 1024 + cm * 32 + bstart + cbl;
            unsigned dstb = sbase + ((cur ^ 1) * BUF1_FLOATS + cbl * HROW + cm * 16) * 4;
            #pragma unroll
            for (int k = 0; k < 16; k++)
                cp_async4(dstb + k * 4, srcb + k * 1024);
        }
        cp_commit();
        cp_wait1();
        __syncthreads();

        uint64_t acc2[8];
        #pragma unroll
        for (int t = 0; t < 8; t++) acc2[t] = 0ull;

        const ulonglong2* xq =
            (const ulonglong2*)(sm + cur * BUF1_FLOATS + warp * HROW);  // lane-uniform
        #pragma unroll
        for (int m = 0; m < 32; m++) {
            uint64_t w2 = splat2(Lreg[m]);
            #pragma unroll
            for (int k = 0; k < 4; k++) {
                ulonglong2 xv = xq[m * 4 + k];       // broadcast LDS.128 = 4 t
                ffma2(acc2[2*k+0], w2, xv.x);
                ffma2(acc2[2*k+1], w2, xv.y);
            }
        }
        __syncthreads();     // buf[cur] reads done before refill

        // STG.128 x4: g_h2[tile][n=lane][b][t], t-contiguous per thread.
        ulonglong2* op = (ulonglong2*)(g_h2 + tile * 16384 + (lane * 32 + b) * 16);
        #pragma unroll
        for (int k = 0; k < 4; k++) {
            ulonglong2 v; v.x = acc2[2*k]; v.y = acc2[2*k+1];
            op[k] = v;
        }

        cur ^= 1;
    }
}

__global__ __launch_bounds__(512, 2)
void monarch_stage2(const float* __restrict__ R, float* __restrict__ out,
                    int ntiles) {
    extern __shared__ float os[];        // os dense XOR: [t][i][slot], 8192 fl
    const int tid  = threadIdx.x;
    const int warp = tid >> 5;           // jl in [0,16)
    const int lane = tid & 31;           // i
    const int half   = blockIdx.x & 1;
    const int jstart = half * 16;
    const int j      = jstart + warp;

    // Weights: Rreg[m] = R[j][i=lane][m]
    float Rreg[32];
    const float4* Rp = (const float4*)(R + j * 1024 + lane * 32);
    #pragma unroll
    for (int q = 0; q < 8; q++) {
        float4 v = Rp[q];
        Rreg[4*q+0] = v.x; Rreg[4*q+1] = v.y; Rreg[4*q+2] = v.z; Rreg[4*q+3] = v.w;
    }

    const int tstride = gridDim.x >> 1;
    const int tile0   = blockIdx.x >> 1;
    const int slot    = warp ^ (lane & 15);   // XOR-swizzled os slot for this warp

    for (int tile = tile0; tile < ntiles; tile += tstride) {
        // Warp slab: g_h2[tile][n=j][*][*] = 512 floats contiguous.
        // Lane-uniform LDG.128 stream; 8 independent FFMA2 chains give ILP.
        const float4* slab = (const float4*)(g_h2 + tile * 16384 + j * 512);

        uint64_t acc2[8];
        #pragma unroll
        for (int t = 0; t < 8; t++) acc2[t] = 0ull;

        #pragma unroll
        for (int m = 0; m < 32; m++) {
            uint64_t w2 = splat2(Rreg[m]);
            #pragma unroll
            for (int k = 0; k < 4; k++) {
                float4 hf = __ldg(slab + m * 4 + k);   // uniform LDG.128 = 4 t
                uint64_t lo, hi;
                asm("mov.b64 %0, {%1, %2};" : "=l"(lo) : "f"(hf.x), "f"(hf.y));
                asm("mov.b64 %0, {%1, %2};" : "=l"(hi) : "f"(hf.z), "f"(hf.w));
                ffma2(acc2[2*k+0], w2, lo);
                ffma2(acc2[2*k+1], w2, hi);
            }
        }

        __syncthreads();     // previous tile's os readout complete

        // Stage: value(t, i=lane, jl=warp) -> os[t*512 + i*16 + (warp^(i&15))]
        #pragma unroll
        for (int k = 0; k < 8; k++) {
            float2 p; *(uint64_t*)&p = acc2[k];
            os[(2*k+0) * 512 + lane * 16 + slot] = p.x;
            os[(2*k+1) * 512 + lane * 16 + slot] = p.y;
        }
        __syncthreads();

        // Coalesced writeout: out[t][i*32 + jstart + jl], reading swizzled os.
        const int t0 = tile * TILE_T;
        #pragma unroll
        for (int f = tid, k = 0; k < 16; f += 512, k++) {
            int jl = f & 15, i2 = (f >> 4) & 31, t = f >> 9;
            out[(t0 + t) * 1024 + i2 * 32 + jstart + jl] =
                os[t * 512 + i2 * 16 + (jl ^ (i2 & 15))];
        }
    }
}

extern "C" void kernel_launch(void* const* d_in, const int* in_sizes, int n_in,
                              void* d_out, int out_size) {
    const float* x = (const float*)d_in[0];
    const float* L = (const float*)d_in[1];
    const float* R = (const float*)d_in[2];
    float* out = (float*)d_out;

    const int ntok   = in_sizes[0] / 1024;   // 32768
    const int ntiles = ntok / TILE_T;        // 2048

    cudaFuncSetAttribute(monarch_stage1,
                         cudaFuncAttributeMaxDynamicSharedMemorySize, SMEM1_BYTES);
    cudaFuncSetAttribute(monarch_stage2,
                         cudaFuncAttributeMaxDynamicSharedMemorySize, SMEM2_BYTES);

    int sms = 148;
    cudaDeviceGetAttribute(&sms, cudaDevAttrMultiProcessorCount, 0);
    int grid = 2 * sms;

    monarch_stage1<<<grid, 512, SMEM1_BYTES>>>(x, L, ntiles);
    monarch_stage2<<<grid, 512, SMEM2_BYTES>>>(R, out, ntiles);
}